// round 5
// baseline (speedup 1.0000x reference)
#include <cuda_runtime.h>
#include <math.h>

// Problem constants
#define KBINS 256
#define Q 4
#define KQ (KBINS * Q)          // 1024 sub-bins
#define BATCH 8
#define NPB (512 * 512)          // 262144 elements per batch
#define NPB4 (NPB / 4)           // 65536 float4 per batch
#define CTAS_PER_BATCH 74        // 8*74 = 592 = 148*4  -> exactly 4 CTAs/SM
#define P1_THREADS 256
#define SCALE 4096.0f            // count-encoding scale
#define WLEN 32                  // convolution window taps, jj in [-14, 17]
#define JJ_LO (-14)

#define PAD4(m) ((m) + ((m) >> 2))   // stride-4 conflict-free padding
#define KQ_PAD (KQ + (KQ >> 2))      // 1280

// Strided per-batch histogram: bin m of batch b lives at g_hist[(b*KQ + m)*8].
// 32B stride puts bin bits into L2 hash bits {8,10..14} -> traffic spreads
// over many LTS slices instead of 8. Footprint 8*1024*32B = 256 KB.
#define HSTRIDE 8
__device__ float g_hist[BATCH * KQ * HSTRIDE];
__device__ unsigned int g_sync[BATCH];

__device__ __forceinline__ void redg_add(float* addr, float v) {
    asm volatile("red.global.add.f32 [%0], %1;" :: "l"(addr), "f"(v) : "memory");
}

// ---------------------------------------------------------------------------
// Fused kernel, direct-REDG variant.
// Phase A (all 592 CTAs, balanced): quantize each x into one of 1024
//   sub-bins and issue ONE red.global.add.f32 per element encoding
//   (count, residual): val = SCALE + r, r in [-0.5, 0.5] sub-bin units.
//   No shared histogram, no flush, no phase-A syncthreads.
//   REDG spread costs 1.29 cyc/lane vs shared ATOMS' 2.0 -> ~1.5x.
// Phase B (last CTA per batch): read the strided batch histogram from L2,
//   decode (cnt, rsum), 32-tap convolution, write 256 outputs, reset state.
// ---------------------------------------------------------------------------
__global__ void __launch_bounds__(P1_THREADS, 8)
hist_fused(const float* __restrict__ x, float* __restrict__ out) {
    __shared__ float pool[2 * KQ_PAD + 2 * WLEN];
    __shared__ bool is_last;

    const int tid = threadIdx.x;
    const int b = blockIdx.y;
    const int c = blockIdx.x;

    float* __restrict__ gh = g_hist + (size_t)b * KQ * HSTRIDE;

    // --- Phase A: direct global reduction over this CTA's balanced range ---
    const float4* __restrict__ xp = reinterpret_cast<const float4*>(x) + (size_t)b * NPB4;
    const int i_lo = (c * NPB4) / CTAS_PER_BATCH;
    const int i_hi = ((c + 1) * NPB4) / CTAS_PER_BATCH;

    for (int i = i_lo + tid; i < i_hi; i += P1_THREADS) {
        float4 v = xp[i];
        float vals[4] = {v.x, v.y, v.z, v.w};
        #pragma unroll
        for (int j = 0; j < 4; j++) {
            float u = vals[j] * (float)KQ;        // position in sub-bin units
            float fidx = floorf(u);
            int idx = (int)fidx;
            idx = max(0, min(KQ - 1, idx));
            // one REDG per element: count (SCALE) + residual (u - fidx - 0.5)
            redg_add(&gh[idx * HSTRIDE], u - fidx + (SCALE - 0.5f));
        }
    }

    // --- Arrival protocol: last CTA of this batch proceeds to phase B ---
    __threadfence();
    if (tid == 0) {
        unsigned int old = atomicAdd(&g_sync[b], 1u);
        is_last = (old == CTAS_PER_BATCH - 1);
    }
    __syncthreads();
    if (!is_last) return;

    // --- Phase B: decode + convolution (one CTA per batch) ---
    float* s_cnt = pool;                    // [KQ_PAD]
    float* s_rs  = pool + KQ_PAD;           // [KQ_PAD]
    float* s_w0  = pool + 2 * KQ_PAD;       // [WLEN]
    float* s_w1  = s_w0 + WLEN;             // [WLEN]

    #pragma unroll
    for (int m = tid; m < KQ; m += P1_THREADS) {
        float s = __ldcg(&gh[m * HSTRIDE]);  // L2-coherent read
        float cnt = rintf(s * (1.0f / SCALE));
        float rs  = s - cnt * SCALE;
        s_cnt[PAD4(m)] = cnt;
        s_rs[PAD4(m)]  = rs;
        gh[m * HSTRIDE] = 0.0f;              // reset for next graph replay
    }
    if (tid == 0) g_sync[b] = 0u;

    // Window weights (float). With Q=4, Delta = 1/1024:
    //   args a+ = 0.625*(jj + 0.5), a- = 0.625*(jj - 3.5)
    //   w0 = sigmoid(a+) - sigmoid(a-);  w1 = 0.625*[sig'(a+) - sig'(a-)]
    if (tid < WLEN) {
        float jj = (float)(tid + JJ_LO);
        float ap = 0.625f * (jj + 0.5f);
        float am = 0.625f * (jj - 3.5f);
        float sp = 1.0f / (1.0f + __expf(-ap));
        float sm = 1.0f / (1.0f + __expf(-am));
        s_w0[tid] = sp - sm;
        s_w1[tid] = (sp * (1.0f - sp) - sm * (1.0f - sm)) * 0.625f;
    }
    __syncthreads();

    // 32-tap convolution per output bin (thread tid = bin k).
    const int base = tid * Q + JJ_LO;
    float acc = 0.0f;
    #pragma unroll
    for (int w = 0; w < WLEN; w++) {
        int m = base + w;
        if (m >= 0 && m < KQ) {
            int mp = PAD4(m);
            acc = fmaf(s_cnt[mp], s_w0[w], acc);
            acc = fmaf(s_rs[mp],  s_w1[w], acc);
        }
    }
    out[b * KBINS + tid] = acc * (1.0f / (float)NPB);
}

extern "C" void kernel_launch(void* const* d_in, const int* in_sizes, int n_in,
                              void* d_out, int out_size) {
    (void)in_sizes; (void)n_in; (void)out_size;
    const float* x = (const float*)d_in[0];
    float* out = (float*)d_out;
    dim3 grid(CTAS_PER_BATCH, BATCH);
    hist_fused<<<grid, P1_THREADS>>>(x, out);
}

// round 6
// speedup vs baseline: 1.3188x; 1.3188x over previous
#include <cuda_runtime.h>
#include <math.h>

// Problem constants
#define KBINS 256
#define Q 4
#define KQ (KBINS * Q)          // 1024 sub-bins
#define BATCH 8
#define NPB (512 * 512)          // 262144 elements per batch
#define NPB4 (NPB / 4)           // 65536 float4 per batch
#define CTAS_PER_BATCH 74        // 8*74 = 592 = 148*4 -> exactly 4 CTAs/SM
#define P1_THREADS 256
#define SCALE 4096.0f            // count-encoding scale
#define WLEN 32                  // convolution window taps, jj in [-14, 17]
#define JJ_LO (-14)

#define PAD4(m) ((m) + ((m) >> 2))   // stride-4 conflict-free padding
#define KQ_PAD (KQ + (KQ >> 2))      // 1280

// Path A target: contiguous per-batch histogram (flushed from shared). 32 KB.
__device__ float g_histA[BATCH * KQ];
// Path B target: 128B-strided per-batch histogram for direct REDG. Bin bits
// land in addr bits 7..16 -> L2 hash bits {8,10..16} -> all LTS slices. 1 MB.
#define HSTRIDE 32
__device__ float g_histB[BATCH * KQ * HSTRIDE];
__device__ unsigned int g_sync[BATCH];

__device__ __forceinline__ void redg_add(float* addr, float v) {
    asm volatile("red.global.add.f32 [%0], %1;" :: "l"(addr), "f"(v) : "memory");
}
__device__ __forceinline__ void red_add_v4(float* addr, float4 v) {
    asm volatile("red.global.add.v4.f32 [%0], {%1,%2,%3,%4};"
                 :: "l"(addr), "f"(v.x), "f"(v.y), "f"(v.z), "f"(v.w)
                 : "memory");
}

// ---------------------------------------------------------------------------
// Fused hybrid kernel.
// Phase A (592 CTAs, balanced): each element -> sub-bin index + encoded
//   (count,residual) value. 5/8 of elements go to the per-CTA SHARED
//   histogram (ATOMS, per-SM LSU pipe); 3/8 go DIRECTLY to the strided
//   global histogram (REDG, L2 slice-ALU pipe). The two atomic pipes are
//   disjoint hardware and run concurrently. Shared histogram flushed with
//   256 v4-REDG per CTA.
// Phase B (last CTA per batch): sum A+B histograms, decode (cnt, rsum),
//   32-tap convolution, write 256 outputs, reset all state for graph replay.
// ---------------------------------------------------------------------------
__global__ void __launch_bounds__(P1_THREADS, 8)
hist_fused(const float* __restrict__ x, float* __restrict__ out) {
    __shared__ float pool[2 * KQ_PAD + 2 * WLEN];   // phase A uses first KQ
    __shared__ bool is_last;
    float* sh = pool;

    const int tid = threadIdx.x;
    const int b = blockIdx.y;
    const int c = blockIdx.x;

    ((float4*)sh)[tid] = make_float4(0.f, 0.f, 0.f, 0.f);
    __syncthreads();

    float* __restrict__ ghA = g_histA + (size_t)b * KQ;
    float* __restrict__ ghB = g_histB + (size_t)b * KQ * HSTRIDE;

    // --- Phase A over this CTA's balanced range ---
    const float4* __restrict__ xp = reinterpret_cast<const float4*>(x) + (size_t)b * NPB4;
    const int i_lo = (c * NPB4) / CTAS_PER_BATCH;
    const int i_hi = ((c + 1) * NPB4) / CTAS_PER_BATCH;

    int it = 0;
    for (int i = i_lo + tid; i < i_hi; i += P1_THREADS, it++) {
        float4 v = xp[i];
        float vals[4] = {v.x, v.y, v.z, v.w};
        // which lanes-of-the-float4 go to the REDG pipe: 1 on even iters,
        // 2 on odd iters -> average 1.5/4 = 3/8 of all elements.
        const int rmask = (it & 1) ? 0xA : 0x8;
        #pragma unroll
        for (int j = 0; j < 4; j++) {
            float u = vals[j] * (float)KQ;        // position in sub-bin units
            float fidx = floorf(u);
            int idx = (int)fidx;
            idx = max(0, min(KQ - 1, idx));
            float enc = u - fidx + (SCALE - 0.5f); // count + residual encode
            if (rmask & (1 << j)) redg_add(&ghB[idx * HSTRIDE], enc);
            else                  atomicAdd(&sh[idx], enc);
        }
    }
    __syncthreads();

    // Flush shared histogram: one v4 reduction per thread.
    {
        float4 vv = ((const float4*)sh)[tid];
        red_add_v4(&ghA[tid * 4], vv);
    }

    // --- Arrival protocol: last CTA of this batch proceeds to phase B ---
    __threadfence();
    if (tid == 0) {
        unsigned int old = atomicAdd(&g_sync[b], 1u);
        is_last = (old == CTAS_PER_BATCH - 1);
    }
    __syncthreads();
    if (!is_last) return;

    // --- Phase B: decode + convolution (one CTA per batch) ---
    float* s_cnt = pool;                    // [KQ_PAD]
    float* s_rs  = pool + KQ_PAD;           // [KQ_PAD]
    float* s_w0  = pool + 2 * KQ_PAD;       // [WLEN]
    float* s_w1  = s_w0 + WLEN;             // [WLEN]

    #pragma unroll
    for (int m = tid; m < KQ; m += P1_THREADS) {
        float s = __ldcg(&ghA[m]) + __ldcg(&ghB[m * HSTRIDE]);
        float cnt = rintf(s * (1.0f / SCALE));
        float rs  = s - cnt * SCALE;
        s_cnt[PAD4(m)] = cnt;
        s_rs[PAD4(m)]  = rs;
        ghA[m] = 0.0f;                      // reset for next graph replay
        ghB[m * HSTRIDE] = 0.0f;
    }
    if (tid == 0) g_sync[b] = 0u;

    // Window weights (float). With Q=4, Delta = 1/1024:
    //   a+ = 0.625*(jj + 0.5), a- = 0.625*(jj - 3.5)
    //   w0 = sigmoid(a+) - sigmoid(a-);  w1 = 0.625*[sig'(a+) - sig'(a-)]
    if (tid < WLEN) {
        float jj = (float)(tid + JJ_LO);
        float ap = 0.625f * (jj + 0.5f);
        float am = 0.625f * (jj - 3.5f);
        float sp = 1.0f / (1.0f + __expf(-ap));
        float sm = 1.0f / (1.0f + __expf(-am));
        s_w0[tid] = sp - sm;
        s_w1[tid] = (sp * (1.0f - sp) - sm * (1.0f - sm)) * 0.625f;
    }
    __syncthreads();

    // 32-tap convolution per output bin (thread tid = bin k).
    const int base = tid * Q + JJ_LO;
    float acc = 0.0f;
    #pragma unroll
    for (int w = 0; w < WLEN; w++) {
        int m = base + w;
        if (m >= 0 && m < KQ) {
            int mp = PAD4(m);
            acc = fmaf(s_cnt[mp], s_w0[w], acc);
            acc = fmaf(s_rs[mp],  s_w1[w], acc);
        }
    }
    out[b * KBINS + tid] = acc * (1.0f / (float)NPB);
}

extern "C" void kernel_launch(void* const* d_in, const int* in_sizes, int n_in,
                              void* d_out, int out_size) {
    (void)in_sizes; (void)n_in; (void)out_size;
    const float* x = (const float*)d_in[0];
    float* out = (float*)d_out;
    dim3 grid(CTAS_PER_BATCH, BATCH);
    hist_fused<<<grid, P1_THREADS>>>(x, out);
}

// round 7
// speedup vs baseline: 1.9142x; 1.4515x over previous
#include <cuda_runtime.h>
#include <math.h>

// Problem constants
#define KBINS 256
#define Q 4
#define KQ (KBINS * Q)          // 1024 sub-bins
#define BATCH 8
#define NPB (512 * 512)          // 262144 elements per batch
#define NPB4 (NPB / 4)           // 65536 float4 per batch
#define CTAS_PER_BATCH 74        // 8*74 = 592 = 148*4 -> exactly 4 CTAs/SM
#define P1_THREADS 256
#define SCALE 4096.0f            // count-encoding scale
#define WLEN 32                  // convolution window taps, jj in [-14, 17]
#define JJ_LO (-14)

#define PAD4(m) ((m) + ((m) >> 2))   // stride-4 conflict-free padding
#define KQ_PAD (KQ + (KQ >> 2))      // 1280

// One combined (cnt,rsum) histogram per batch: 8 * 1024 * 4B = 32 KB.
// Zero at module load; the finishing CTA re-zeroes it each launch so the
// kernel is graph-replay deterministic.
__device__ float g_hist[BATCH * KQ];
__device__ unsigned int g_sync[BATCH];

__device__ __forceinline__ void red_add_v4(float* addr, float4 v) {
    asm volatile("red.global.add.v4.f32 [%0], {%1,%2,%3,%4};"
                 :: "l"(addr), "f"(v.x), "f"(v.y), "f"(v.z), "f"(v.w)
                 : "memory");
}

// ---------------------------------------------------------------------------
// Fused kernel (pure shared-ATOMS — measured hardware floor ~2 cyc/element
// of the per-SM smem port; R5/R6 established that REDG offload head-of-line
// blocks the same LSU FIFO and is strictly worse).
// Phase A (592 CTAs, perfectly balanced): quantize each x into one of 1024
//   sub-bins; ONE shared atomicAdd per element encoding (count, residual):
//   val = SCALE + r, r in [-0.5, 0.5] sub-bin units. Flush the 4KB shared
//   histogram with one red.global.add.v4.f32 per thread.
// Phase B (last CTA per batch): read the 4KB batch histogram from L2,
//   decode (cnt, rsum), 32-tap convolution, write 256 outputs, reset state.
// ---------------------------------------------------------------------------
__global__ void __launch_bounds__(P1_THREADS, 8)
hist_fused(const float* __restrict__ x, float* __restrict__ out) {
    __shared__ float pool[2 * KQ_PAD + 2 * WLEN];   // phase A uses first KQ
    __shared__ bool is_last;
    float* sh = pool;

    const int tid = threadIdx.x;
    const int b = blockIdx.y;
    const int c = blockIdx.x;

    ((float4*)sh)[tid] = make_float4(0.f, 0.f, 0.f, 0.f);
    __syncthreads();

    // --- Phase A: local accumulation over this CTA's balanced range ---
    const float4* __restrict__ xp = reinterpret_cast<const float4*>(x) + (size_t)b * NPB4;
    const int i_lo = (c * NPB4) / CTAS_PER_BATCH;
    const int i_hi = ((c + 1) * NPB4) / CTAS_PER_BATCH;

    #pragma unroll 2
    for (int i = i_lo + tid; i < i_hi; i += P1_THREADS) {
        float4 v = xp[i];
        float vals[4] = {v.x, v.y, v.z, v.w};
        #pragma unroll
        for (int j = 0; j < 4; j++) {
            float u = vals[j] * (float)KQ;        // position in sub-bin units
            int idx = __float2int_rd(u);          // floor as direct F2I.FLOOR
            idx = max(0, min(KQ - 1, idx));
            // one ATOMS per element: count (SCALE) + residual (u - idx - 0.5)
            atomicAdd(&sh[idx], u - (float)idx + (SCALE - 0.5f));
        }
    }
    __syncthreads();

    // Flush: one v4 reduction per thread (1024 bins / 4 / 256 threads).
    float* __restrict__ gh = g_hist + (size_t)b * KQ;
    {
        float4 vv = ((const float4*)sh)[tid];
        red_add_v4(&gh[tid * 4], vv);
    }

    // --- Arrival protocol: last CTA of this batch proceeds to phase B ---
    __threadfence();
    if (tid == 0) {
        unsigned int old = atomicAdd(&g_sync[b], 1u);
        is_last = (old == CTAS_PER_BATCH - 1);
    }
    __syncthreads();
    if (!is_last) return;

    // --- Phase B: decode + convolution (one CTA per batch) ---
    float* s_cnt = pool;                    // [KQ_PAD]
    float* s_rs  = pool + KQ_PAD;           // [KQ_PAD]
    float* s_w0  = pool + 2 * KQ_PAD;       // [WLEN]
    float* s_w1  = s_w0 + WLEN;             // [WLEN]

    #pragma unroll
    for (int m = tid; m < KQ; m += P1_THREADS) {
        float s = __ldcg(&gh[m]);           // L2-coherent read
        float cnt = rintf(s * (1.0f / SCALE));
        float rs  = s - cnt * SCALE;
        s_cnt[PAD4(m)] = cnt;
        s_rs[PAD4(m)]  = rs;
        gh[m] = 0.0f;                       // reset for next graph replay
    }
    if (tid == 0) g_sync[b] = 0u;

    // Window weights (float). With Q=4, Delta = 1/1024:
    //   a+ = 0.625*(jj + 0.5), a- = 0.625*(jj - 3.5)
    //   w0 = sigmoid(a+) - sigmoid(a-);  w1 = 0.625*[sig'(a+) - sig'(a-)]
    if (tid < WLEN) {
        float jj = (float)(tid + JJ_LO);
        float ap = 0.625f * (jj + 0.5f);
        float am = 0.625f * (jj - 3.5f);
        float sp = 1.0f / (1.0f + __expf(-ap));
        float sm = 1.0f / (1.0f + __expf(-am));
        s_w0[tid] = sp - sm;
        s_w1[tid] = (sp * (1.0f - sp) - sm * (1.0f - sm)) * 0.625f;
    }
    __syncthreads();

    // 32-tap convolution per output bin (thread tid = bin k).
    const int base = tid * Q + JJ_LO;
    float acc = 0.0f;
    #pragma unroll
    for (int w = 0; w < WLEN; w++) {
        int m = base + w;
        if (m >= 0 && m < KQ) {
            int mp = PAD4(m);
            acc = fmaf(s_cnt[mp], s_w0[w], acc);
            acc = fmaf(s_rs[mp],  s_w1[w], acc);
        }
    }
    out[b * KBINS + tid] = acc * (1.0f / (float)NPB);
}

extern "C" void kernel_launch(void* const* d_in, const int* in_sizes, int n_in,
                              void* d_out, int out_size) {
    (void)in_sizes; (void)n_in; (void)out_size;
    const float* x = (const float*)d_in[0];
    float* out = (float*)d_out;
    dim3 grid(CTAS_PER_BATCH, BATCH);
    hist_fused<<<grid, P1_THREADS>>>(x, out);
}